// round 16
// baseline (speedup 1.0000x reference)
#include <cuda_runtime.h>
#include <cuda_bf16.h>
#include <math.h>
#include <stddef.h>
#include <stdint.h>

// Problem dims
#define BV 7800
#define BVP 7808
#define DD 300
#define DPK 320
#define RR 512
#define HH 512
#define FEAT 2048
#define BB 128
#define AA 196
#define TT 20
#define A1 197
#define G5 2560
#define MROWS 25088
#define OUT_ROW 156000
#define GRIDP 128

// ---------------- device scratch ----------------
__device__ __nv_bfloat16 g_att_bf[MROWS * FEAT];
__device__ __nv_bfloat16 g_aeW_bf[RR * FEAT];
__device__ __nv_bfloat16 g_c2aW_bf[RR * RR];
__device__ __nv_bfloat16 g_whh_bf[G5 * RR];
__device__ __nv_bfloat16 g_seW_bf[HH * RR];
__device__ __nv_bfloat16 g_hoW_bf[HH * RR];
__device__ __nv_bfloat16 g_a2hW_bf[RR * RR];
__device__ __nv_bfloat16 g_v_bf[MROWS * RR];
__device__ __nv_bfloat16 g_vemb_bf[MROWS * RR];
__device__ __nv_bfloat16 g_xall_bf[TT * BB * DPK];
__device__ __nv_bfloat16 g_wih_bf[G5 * DPK];
__device__ __nv_bfloat16 g_lgW_bf[BVP * RR];
__device__ __nv_bfloat16 g_hout_all[TT * BB * RR];
__device__ __nv_bfloat16 g_h_bf[BB * RR];
__device__ __nv_bfloat16 g_sent_bf[BB * RR];
__device__ __nv_bfloat16 g_x2_bf[BB * RR];
__device__ float g_gx[TT * BB * G5];
__device__ float g_gates[BB * G5];
__device__ float g_h[BB * RR];
__device__ float g_c[BB * RR];
__device__ float g_sentemb[BB * HH];
__device__ float g_hemb[BB * HH];
__device__ unsigned g_bar_count = 0;
__device__ volatile unsigned g_bar_sense = 0;

// ---------------- static stream/event resources ----------------
static cudaStream_t s_b = nullptr;
static cudaEvent_t s_evFork = nullptr, s_evGx = nullptr;
static struct StreamInit {
    StreamInit() {
        cudaStreamCreateWithFlags(&s_b, cudaStreamNonBlocking);
        cudaEventCreateWithFlags(&s_evFork, cudaEventDisableTiming);
        cudaEventCreateWithFlags(&s_evGx, cudaEventDisableTiming);
    }
} s_streamInit;

// ---------------- helpers ----------------
__device__ __forceinline__ float sigmoidf_(float x) { return 1.0f / (1.0f + expf(-x)); }
__device__ __forceinline__ float tanh_fast(float x) {
    float y;
    asm("tanh.approx.f32 %0, %1;" : "=f"(y) : "f"(x));
    return y;
}
__device__ __forceinline__ void mma16816(float* c, const uint32_t* a, uint32_t b0, uint32_t b1) {
    asm volatile(
        "mma.sync.aligned.m16n8k16.row.col.f32.bf16.bf16.f32 "
        "{%0,%1,%2,%3}, {%4,%5,%6,%7}, {%8,%9}, {%0,%1,%2,%3};"
        : "+f"(c[0]), "+f"(c[1]), "+f"(c[2]), "+f"(c[3])
        : "r"(a[0]), "r"(a[1]), "r"(a[2]), "r"(a[3]), "r"(b0), "r"(b1));
}
__device__ __forceinline__ void ldsm4(uint32_t* r, uint32_t addr) {
    asm volatile("ldmatrix.sync.aligned.m8n8.x4.shared.b16 {%0,%1,%2,%3}, [%4];"
                 : "=r"(r[0]), "=r"(r[1]), "=r"(r[2]), "=r"(r[3]) : "r"(addr));
}
__device__ __forceinline__ void cpa16(uint32_t dst, const void* src) {
    asm volatile("cp.async.cg.shared.global [%0], [%1], 16;" :: "r"(dst), "l"(src));
}
#define CP_COMMIT() asm volatile("cp.async.commit_group;" ::: "memory")
#define CP_WAIT3()  asm volatile("cp.async.wait_group 3;" ::: "memory")
#define CP_WAIT1()  asm volatile("cp.async.wait_group 1;" ::: "memory")
#define CP_WAIT0()  asm volatile("cp.async.wait_group 0;" ::: "memory")

__device__ __forceinline__ void gbar(unsigned sense) {
    __syncthreads();
    if (threadIdx.x == 0) {
        __threadfence();
        unsigned arrived = atomicAdd(&g_bar_count, 1u);
        if (arrived == GRIDP - 1) {
            g_bar_count = 0;
            __threadfence();
            g_bar_sense = sense;
        } else {
            while (g_bar_sense != sense) __nanosleep(32);
        }
        __threadfence();
    }
    __syncthreads();
}

// ---------------- bf16 mma.sync GEMM: 128x128 tile, LDSM, 2-stage (proven) ----
#define PADR 40
#define BUFW (128 * PADR)
struct MmaSmem { __nv_bfloat16 sA[2][BUFW]; __nv_bfloat16 sB[2][BUFW]; };

template <int ACT, bool HAS_BIAS, bool WF32, bool WBF, bool HAS_CIN, bool OUTMAP>
__device__ __forceinline__ void mma_body(
    MmaSmem& sm,
    const __nv_bfloat16* __restrict__ A, const __nv_bfloat16* __restrict__ W,
    const float* __restrict__ bias, const float* __restrict__ Cin,
    float* __restrict__ C, __nv_bfloat16* __restrict__ Cbf,
    int Nlog, int K, size_t ldc, int ldcin, int ldbf, int bm, int bn) {

    int tid = threadIdx.x;
    int wid = tid >> 5, lane = tid & 31;
    int wm = wid >> 1, wn = wid & 1;
    int g = lane >> 2, tg = lane & 3;
    int lr8 = lane & 7;

    int r0g = tid >> 2, s0g = tid & 3;
    int r1g = (tid + 256) >> 2;
    const char* Ag0 = (const char*)(A + (size_t)(bm + r0g) * K + s0g * 8);
    const char* Ag1 = (const char*)(A + (size_t)(bm + r1g) * K + s0g * 8);
    const char* Wg0 = (const char*)(W + (size_t)(bn + r0g) * K + s0g * 8);
    const char* Wg1 = (const char*)(W + (size_t)(bn + r1g) * K + s0g * 8);
    uint32_t aBase = (uint32_t)__cvta_generic_to_shared(&sm.sA[0][0]);
    uint32_t bBase = (uint32_t)__cvta_generic_to_shared(&sm.sB[0][0]);
    uint32_t dA0 = aBase + r0g * (PADR * 2) + s0g * 16;
    uint32_t dA1 = aBase + r1g * (PADR * 2) + s0g * 16;
    uint32_t dB0 = bBase + r0g * (PADR * 2) + s0g * 16;
    uint32_t dB1 = bBase + r1g * (PADR * 2) + s0g * 16;

    uint32_t aAddr = aBase + (uint32_t)(wm * 32 + lr8 + ((lane >> 3) & 1) * 8) * 80
                     + (uint32_t)(lane >> 4) * 16;
    uint32_t bAddr = bBase + (uint32_t)(wn * 64 + lr8 + (lane >> 4) * 8) * 80
                     + (uint32_t)((lane >> 3) & 1) * 16;

    float acc[2][8][4];
#pragma unroll
    for (int m = 0; m < 2; m++)
#pragma unroll
        for (int n = 0; n < 8; n++)
#pragma unroll
            for (int q = 0; q < 4; q++) acc[m][n][q] = 0.0f;

    cpa16(dA0, Ag0); cpa16(dA1, Ag1);
    cpa16(dB0, Wg0); cpa16(dB1, Wg1);
    CP_COMMIT();

    for (int k0 = 0; k0 < K; k0 += 32) {
        int cur = (k0 >> 5) & 1;
        if (k0 + 32 < K) {
            uint32_t off = (cur ^ 1) * (BUFW * 2);
            size_t kb = (size_t)(k0 + 32) * 2;
            cpa16(dA0 + off, Ag0 + kb); cpa16(dA1 + off, Ag1 + kb);
            cpa16(dB0 + off, Wg0 + kb); cpa16(dB1 + off, Wg1 + kb);
            CP_COMMIT();
            CP_WAIT1();
        } else {
            CP_WAIT0();
        }
        __syncthreads();
        uint32_t so = cur * (BUFW * 2);
#pragma unroll
        for (int ks = 0; ks < 2; ks++) {
            uint32_t aF[2][4];
            ldsm4(aF[0], aAddr + so + ks * 32);
            ldsm4(aF[1], aAddr + so + 16 * 80 + ks * 32);
            uint32_t bF[4][4];
#pragma unroll
            for (int np = 0; np < 4; np++)
                ldsm4(bF[np], bAddr + so + np * 16 * 80 + ks * 32);
#pragma unroll
            for (int n = 0; n < 8; n++) {
                uint32_t b0 = bF[n >> 1][(n & 1) * 2];
                uint32_t b1 = bF[n >> 1][(n & 1) * 2 + 1];
                mma16816(acc[0][n], aF[0], b0, b1);
                mma16816(acc[1][n], aF[1], b0, b1);
            }
        }
        __syncthreads();
    }

#pragma unroll
    for (int m = 0; m < 2; m++) {
        int row0 = bm + wm * 32 + m * 16 + g;
#pragma unroll
        for (int n = 0; n < 8; n++) {
            int col = bn + wn * 64 + n * 8 + tg * 2;
            float v0 = acc[m][n][0], v1 = acc[m][n][1];
            float v2 = acc[m][n][2], v3 = acc[m][n][3];
            if (HAS_BIAS) {
                if (col < Nlog) { float bb = bias[col]; v0 += bb; v2 += bb; }
                if (col + 1 < Nlog) { float bb = bias[col + 1]; v1 += bb; v3 += bb; }
            }
            if (HAS_CIN) {
                float2 c0 = *(const float2*)(Cin + (size_t)row0 * ldcin + col);
                float2 c1 = *(const float2*)(Cin + (size_t)(row0 + 8) * ldcin + col);
                v0 += c0.x; v1 += c0.y; v2 += c1.x; v3 += c1.y;
            }
            if (ACT == 1) {
                v0 = fmaxf(v0, 0.f); v1 = fmaxf(v1, 0.f);
                v2 = fmaxf(v2, 0.f); v3 = fmaxf(v3, 0.f);
            } else if (ACT == 2) {
                v0 = tanhf(v0); v1 = tanhf(v1); v2 = tanhf(v2); v3 = tanhf(v3);
            }
            if (WF32) {
                size_t ra, rb2;
                if (OUTMAP) {
                    ra = (size_t)(row0 & 127) * OUT_ROW + (size_t)(row0 >> 7) * BV;
                    rb2 = (size_t)((row0 + 8) & 127) * OUT_ROW + (size_t)((row0 + 8) >> 7) * BV;
                } else {
                    ra = (size_t)row0 * ldc;
                    rb2 = (size_t)(row0 + 8) * ldc;
                }
                if (col + 1 < Nlog) {
                    *(float2*)(C + ra + col) = make_float2(v0, v1);
                    *(float2*)(C + rb2 + col) = make_float2(v2, v3);
                } else if (col < Nlog) {
                    C[ra + col] = v0;
                    C[rb2 + col] = v2;
                }
            }
            if (WBF) {
                *(__nv_bfloat162*)(Cbf + (size_t)row0 * ldbf + col) =
                    __floats2bfloat162_rn(v0, v1);
                *(__nv_bfloat162*)(Cbf + (size_t)(row0 + 8) * ldbf + col) =
                    __floats2bfloat162_rn(v2, v3);
            }
        }
    }
}

template <int ACT, bool HAS_BIAS, bool WF32, bool WBF, bool HAS_CIN, bool OUTMAP>
__global__ void __launch_bounds__(256, 2) gemm_mma(
    const __nv_bfloat16* __restrict__ A, const __nv_bfloat16* __restrict__ W,
    const float* __restrict__ bias, const float* __restrict__ Cin,
    float* __restrict__ C, __nv_bfloat16* __restrict__ Cbf,
    int Nlog, int K, size_t ldc, int ldcin, int ldbf) {
    __shared__ MmaSmem sm;
    mma_body<ACT, HAS_BIAS, WF32, WBF, HAS_CIN, OUTMAP>(
        sm, A, W, bias, Cin, C, Cbf, Nlog, K, ldc, ldcin, ldbf,
        blockIdx.x * 128, blockIdx.y * 128);
}

// ---------------- resident-B GEMM: 4-stage A pipeline, LDSM (proven) ----------
#define BROW 520
#define ASTAGES 4
template <int ACT, bool HAS_BIAS, bool WF32, bool WBF, bool HAS_CIN>
__device__ __forceinline__ void mma_resB(
    const __nv_bfloat16* __restrict__ sB, __nv_bfloat16* __restrict__ sAb,
    const __nv_bfloat16* __restrict__ A,
    const float* __restrict__ bias, const float* __restrict__ Cin,
    float* __restrict__ C, __nv_bfloat16* __restrict__ Cbf,
    size_t ldc, int ldcin, int ldbf, int bn) {

    int tid = threadIdx.x;
    int wid = tid >> 5, lane = tid & 31;
    int wm = wid >> 1, wn = wid & 1;
    int g = lane >> 2, tg = lane & 3;
    int lr8 = lane & 7;

    int r0g = tid >> 2, s0g = tid & 3;
    const char* Ag0 = (const char*)(A + (size_t)r0g * RR + s0g * 8);
    const char* Ag1 = (const char*)(A + (size_t)(r0g + 64) * RR + s0g * 8);
    uint32_t ab = (uint32_t)__cvta_generic_to_shared(sAb);
    uint32_t bb = (uint32_t)__cvta_generic_to_shared(sB);
    uint32_t dA0 = ab + r0g * (PADR * 2) + s0g * 16;
    uint32_t dA1 = ab + (r0g + 64) * (PADR * 2) + s0g * 16;

    uint32_t aAddr = ab + (uint32_t)(wm * 32 + lr8 + ((lane >> 3) & 1) * 8) * 80
                     + (uint32_t)(lane >> 4) * 16;
    uint32_t bAddr = bb + (uint32_t)(wn * 64 + lr8 + (lane >> 4) * 8) * 1040
                     + (uint32_t)((lane >> 3) & 1) * 16;

    float acc[2][8][4];
#pragma unroll
    for (int m = 0; m < 2; m++)
#pragma unroll
        for (int n = 0; n < 8; n++)
#pragma unroll
            for (int q = 0; q < 4; q++) acc[m][n][q] = 0.0f;

#pragma unroll
    for (int s = 0; s < 3; s++) {
        uint32_t off = s * (BUFW * 2);
        size_t kb = (size_t)(s << 5) * 2;
        cpa16(dA0 + off, Ag0 + kb); cpa16(dA1 + off, Ag1 + kb);
        CP_COMMIT();
    }

    for (int i = 0; i < 16; i++) {
        if (i + 3 < 16) {
            uint32_t off = ((i + 3) & 3) * (BUFW * 2);
            size_t kb = (size_t)((i + 3) << 5) * 2;
            cpa16(dA0 + off, Ag0 + kb); cpa16(dA1 + off, Ag1 + kb);
        }
        CP_COMMIT();
        CP_WAIT3();
        __syncthreads();
        uint32_t so = (i & 3) * (BUFW * 2);
        uint32_t kb64 = (uint32_t)i * 64;
#pragma unroll
        for (int ks = 0; ks < 2; ks++) {
            uint32_t aF[2][4];
            ldsm4(aF[0], aAddr + so + ks * 32);
            ldsm4(aF[1], aAddr + so + 16 * 80 + ks * 32);
            uint32_t bF[4][4];
#pragma unroll
            for (int np = 0; np < 4; np++)
                ldsm4(bF[np], bAddr + np * 16 * 1040 + kb64 + ks * 32);
#pragma unroll
            for (int n = 0; n < 8; n++) {
                uint32_t b0 = bF[n >> 1][(n & 1) * 2];
                uint32_t b1 = bF[n >> 1][(n & 1) * 2 + 1];
                mma16816(acc[0][n], aF[0], b0, b1);
                mma16816(acc[1][n], aF[1], b0, b1);
            }
        }
        __syncthreads();
    }

#pragma unroll
    for (int m = 0; m < 2; m++) {
        int row0 = wm * 32 + m * 16 + g;
#pragma unroll
        for (int n = 0; n < 8; n++) {
            int col = bn + wn * 64 + n * 8 + tg * 2;
            float v0 = acc[m][n][0], v1 = acc[m][n][1];
            float v2 = acc[m][n][2], v3 = acc[m][n][3];
            if (HAS_BIAS) {
                float b0 = bias[col], b1 = bias[col + 1];
                v0 += b0; v1 += b1; v2 += b0; v3 += b1;
            }
            if (HAS_CIN) {
                float2 c0 = *(const float2*)(Cin + (size_t)row0 * ldcin + col);
                float2 c1 = *(const float2*)(Cin + (size_t)(row0 + 8) * ldcin + col);
                v0 += c0.x; v1 += c0.y; v2 += c1.x; v3 += c1.y;
            }
            if (ACT == 2) { v0 = tanhf(v0); v1 = tanhf(v1); v2 = tanhf(v2); v3 = tanhf(v3); }
            if (WF32) {
                *(float2*)(C + (size_t)row0 * ldc + col) = make_float2(v0, v1);
                *(float2*)(C + (size_t)(row0 + 8) * ldc + col) = make_float2(v2, v3);
            }
            if (WBF) {
                *(__nv_bfloat162*)(Cbf + (size_t)row0 * ldbf + col) =
                    __floats2bfloat162_rn(v0, v1);
                *(__nv_bfloat162*)(Cbf + (size_t)(row0 + 8) * ldbf + col) =
                    __floats2bfloat162_rn(v2, v3);
            }
        }
    }
}

// ---------------- persistent step-loop (in-loop logits + log-softmax) ----------------
#define SM_BRES 133120
#define SM_STEP (SM_BRES + ASTAGES * BUFW * 2)
struct AttnSmem { float sAl[HH]; float sH[HH]; float sSc[224]; float red[256]; };

__global__ void __launch_bounds__(256) step_loop_kernel(
    const __nv_bfloat16* __restrict__ whh_bf, const float* __restrict__ gx,
    float* __restrict__ gates, float* __restrict__ h, float* __restrict__ c,
    __nv_bfloat16* __restrict__ h_bf, __nv_bfloat16* __restrict__ sent_bf,
    const __nv_bfloat16* __restrict__ seW_bf, const __nv_bfloat16* __restrict__ hoW_bf,
    const float* __restrict__ seb, const float* __restrict__ hob,
    float* __restrict__ sentemb, float* __restrict__ hemb,
    const __nv_bfloat16* __restrict__ vemb_bf, const float* __restrict__ alW,
    const float* __restrict__ alb, const __nv_bfloat16* __restrict__ v_bf,
    __nv_bfloat16* __restrict__ x2_bf,
    const __nv_bfloat16* __restrict__ a2hW_bf, const float* __restrict__ a2hb,
    __nv_bfloat16* __restrict__ hout_all,
    const __nv_bfloat16* __restrict__ lgW_bf, const float* __restrict__ lgb,
    float* __restrict__ out) {
    extern __shared__ char dsm[];
    __nv_bfloat16* sB = (__nv_bfloat16*)dsm;
    __nv_bfloat16* sAb = (__nv_bfloat16*)(dsm + SM_BRES);
    AttnSmem* at = (AttnSmem*)(dsm + SM_BRES);
    MmaSmem* lsm = (MmaSmem*)dsm;   // logits CTAs (>=32): sB region is scratch

    int blk = blockIdx.x;
    int tid = threadIdx.x;
    unsigned sense = g_bar_sense;

    const __nv_bfloat16* myW = nullptr;
    if (blk < 20) myW = whh_bf + (size_t)blk * 128 * RR;
    else if (blk < 24) myW = seW_bf + (size_t)(blk - 20) * 128 * RR;
    else if (blk < 28) myW = hoW_bf + (size_t)(blk - 24) * 128 * RR;
    else if (blk < 32) myW = a2hW_bf + (size_t)(blk - 28) * 128 * RR;
    if (myW) {
        const uint4* src = (const uint4*)myW;
        for (int i = tid; i < 128 * 64; i += 256) {
            int r = i >> 6, cq = i & 63;
            ((uint4*)(sB + (size_t)r * BROW))[cq] = src[r * 64 + cq];
        }
    }
    __syncthreads();

    if (blk < 20)
        mma_resB<0, false, true, false, true>(sB, sAb, h_bf, nullptr, gx, gates,
                                              nullptr, G5, G5, 0, blk * 128);
    sense ^= 1; gbar(sense);

    for (int t = 0; t < TT; t++) {
        {
            int base = blk * 512 + tid;
#pragma unroll
            for (int u = 0; u < 2; u++) {
                int idx = base + u * 256;
                int b = idx >> 9, r = idx & 511;
                const float* gg = gates + (size_t)b * G5;
                float ig = sigmoidf_(gg[r]);
                float fg = sigmoidf_(gg[RR + r]);
                float g2 = tanhf(gg[2 * RR + r]);
                float og = sigmoidf_(gg[3 * RR + r]);
                float sg = sigmoidf_(gg[4 * RR + r]);
                float cy = tanhf(fg * c[idx] + ig * g2);
                c[idx] = cy;
                float hy = og * cy;
                h[idx] = hy;
                h_bf[idx] = __float2bfloat16(hy);
                sent_bf[idx] = __float2bfloat16(sg * cy);
            }
        }
        sense ^= 1; gbar(sense);

        if (blk >= 20 && blk < 24)
            mma_resB<0, true, true, false, false>(sB, sAb, sent_bf, seb, nullptr,
                                                  sentemb, nullptr, HH, 0, 0,
                                                  (blk - 20) * 128);
        else if (blk >= 24 && blk < 28)
            mma_resB<0, true, true, false, false>(sB, sAb, h_bf, hob, nullptr,
                                                  hemb, nullptr, HH, 0, 0,
                                                  (blk - 24) * 128);
        sense ^= 1; gbar(sense);

        {
            int b = blk;
            float* sAl = at->sAl;
            float* sH = at->sH;
            float* sSc = at->sSc;
            float* red = at->red;
            for (int j = tid; j < HH; j += 256) {
                sAl[j] = alW[j];
                sH[j] = hemb[(size_t)b * HH + j];
            }
            __syncthreads();
            int warp = tid >> 5, lane = tid & 31;
            float ab = alb[0];
            for (int a = warp; a < A1; a += 8) {
                float s = 0.0f;
                if (a == 0) {
                    const float2* e2 = (const float2*)(sentemb + (size_t)b * HH);
                    for (int j2 = lane; j2 < 256; j2 += 32) {
                        float2 ev = e2[j2];
                        int j = j2 * 2;
                        s += sAl[j] * tanh_fast(ev.x + sH[j]);
                        s += sAl[j + 1] * tanh_fast(ev.y + sH[j + 1]);
                    }
                } else {
                    const __nv_bfloat162* e2 =
                        (const __nv_bfloat162*)(vemb_bf + ((size_t)b * AA + (a - 1)) * HH);
                    for (int j2 = lane; j2 < 256; j2 += 32) {
                        __nv_bfloat162 ev = e2[j2];
                        int j = j2 * 2;
                        s += sAl[j] * tanh_fast(__low2float(ev) + sH[j]);
                        s += sAl[j + 1] * tanh_fast(__high2float(ev) + sH[j + 1]);
                    }
                }
#pragma unroll
                for (int o = 16; o > 0; o >>= 1) s += __shfl_down_sync(0xffffffffu, s, o);
                if (lane == 0) sSc[a] = s + ab;
            }
            __syncthreads();
            float m = -INFINITY;
            for (int a = tid; a < A1; a += 256) m = fmaxf(m, sSc[a]);
            red[tid] = m; __syncthreads();
            for (int st = 128; st > 0; st >>= 1) {
                if (tid < st) red[tid] = fmaxf(red[tid], red[tid + st]);
                __syncthreads();
            }
            float mx = red[0]; __syncthreads();
            float sum = 0.0f;
            for (int a = tid; a < A1; a += 256) sum += expf(sSc[a] - mx);
            red[tid] = sum; __syncthreads();
            for (int st = 128; st > 0; st >>= 1) {
                if (tid < st) red[tid] += red[tid + st];
                __syncthreads();
            }
            float inv = 1.0f / red[0];
            __syncthreads();
            for (int a = tid; a < A1; a += 256) sSc[a] = expf(sSc[a] - mx) * inv;
            __syncthreads();
            const __nv_bfloat162* vp2 = (const __nv_bfloat162*)(v_bf + (size_t)b * AA * RR);
            __nv_bfloat162 sv = ((const __nv_bfloat162*)(sent_bf + (size_t)b * RR))[tid];
            float a0 = sSc[0];
            float acc0 = a0 * __low2float(sv);
            float acc1 = a0 * __high2float(sv);
            for (int a = 0; a < AA; a++) {
                __nv_bfloat162 vv = vp2[(size_t)a * (RR / 2) + tid];
                float s = sSc[a + 1];
                acc0 += s * __low2float(vv);
                acc1 += s * __high2float(vv);
            }
            float2 hv = *(const float2*)(h + (size_t)b * RR + 2 * tid);
            ((__nv_bfloat162*)(x2_bf + (size_t)b * RR))[tid] =
                __floats2bfloat162_rn(acc0 + hv.x, acc1 + hv.y);
            __syncthreads();
        }
        sense ^= 1; gbar(sense);

        // P5: a2h (28-31) || P1(t+1) (0-19) || logits(t-1) (32-92) || logsm(t-2) (93-127)
        if (blk >= 28 && blk < 32)
            mma_resB<2, true, false, true, false>(sB, sAb, x2_bf, a2hb, nullptr,
                                                  nullptr, hout_all + (size_t)t * BB * RR,
                                                  0, 0, RR, (blk - 28) * 128);
        else if (blk < 20 && t + 1 < TT)
            mma_resB<0, false, true, false, true>(sB, sAb, h_bf, nullptr,
                                                  gx + (size_t)(t + 1) * BB * G5, gates,
                                                  nullptr, G5, G5, 0, blk * 128);
        else if (blk >= 32 && blk < 32 + BVP / 128 && t >= 1)
            mma_body<0, true, true, false, false, false>(
                *lsm, hout_all + (size_t)(t - 1) * BB * RR, lgW_bf, lgb, nullptr,
                out + (size_t)(t - 1) * BV, nullptr, BV, RR, OUT_ROW, 0, 0,
                0, (blk - 32) * 128);
        else if (blk >= 93 && t >= 2) {
            float* red = at->red;
            for (int b = blk - 93; b < BB; b += 35) {
                float* p = out + (size_t)b * OUT_ROW + (size_t)(t - 2) * BV;
                float m = -INFINITY;
                for (int i = tid; i < BV; i += 256) m = fmaxf(m, p[i]);
                red[tid] = m; __syncthreads();
                for (int st = 128; st > 0; st >>= 1) {
                    if (tid < st) red[tid] = fmaxf(red[tid], red[tid + st]);
                    __syncthreads();
                }
                float mx = red[0]; __syncthreads();
                float sum = 0.0f;
                for (int i = tid; i < BV; i += 256) sum += expf(p[i] - mx);
                red[tid] = sum; __syncthreads();
                for (int st = 128; st > 0; st >>= 1) {
                    if (tid < st) red[tid] += red[tid + st];
                    __syncthreads();
                }
                float lse = mx + logf(red[0]);
                __syncthreads();
                for (int i = tid; i < BV; i += 256) p[i] -= lse;
            }
        }
        sense ^= 1; gbar(sense);
    }
}

// ---------------- conversions ----------------
__global__ void cvt_f2b4(const float* __restrict__ in, __nv_bfloat16* __restrict__ out, int n4) {
    int i = blockIdx.x * blockDim.x + threadIdx.x;
    if (i >= n4) return;
    float4 v = ((const float4*)in)[i];
    __nv_bfloat162* p = (__nv_bfloat162*)out + i * 2;
    p[0] = __floats2bfloat162_rn(v.x, v.y);
    p[1] = __floats2bfloat162_rn(v.z, v.w);
}
__global__ void pad_wih_bf(const float* __restrict__ w, __nv_bfloat16* __restrict__ wp) {
    int idx = blockIdx.x * blockDim.x + threadIdx.x;
    if (idx >= G5 * DPK) return;
    int r = idx / DPK, c = idx % DPK;
    wp[idx] = (c < DD) ? __float2bfloat16(w[r * DD + c]) : __float2bfloat16(0.0f);
}
__global__ void pad_lgw_bf(const float* __restrict__ w, __nv_bfloat16* __restrict__ wp) {
    int idx = blockIdx.x * blockDim.x + threadIdx.x;
    if (idx >= BVP * RR) return;
    int r = idx / RR, c = idx % RR;
    wp[idx] = (r < BV) ? __float2bfloat16(w[(size_t)r * RR + c]) : __float2bfloat16(0.0f);
}
__global__ void embed_all_bf(const int* __restrict__ seq, const float* __restrict__ E,
                             __nv_bfloat16* __restrict__ xall) {
    int idx = blockIdx.x * blockDim.x + threadIdx.x;
    if (idx >= TT * BB * DPK) return;
    int d = idx % DPK;
    int row = idx / DPK;
    int t = row / BB, b = row % BB;
    float v = 0.0f;
    if (d < DD) {
        int tok = seq[b * 21 + t];
        v = fmaxf(E[(size_t)tok * DD + d], 0.0f);
    }
    xall[idx] = __float2bfloat16(v);
}
__global__ void init_state_kernel(float* h, float* c, __nv_bfloat16* h_bf) {
    int i = blockIdx.x * blockDim.x + threadIdx.x;
    if (i < BB * RR) { h[i] = 0.0f; c[i] = 0.0f; h_bf[i] = __float2bfloat16(0.0f); }
}

// ---------------- batched log-softmax (tail steps) ----------------
__global__ void __launch_bounds__(256) logsm_all(float* __restrict__ out) {
    float* p = out + (size_t)blockIdx.x * OUT_ROW + (size_t)blockIdx.y * BV;
    __shared__ float red[256];
    int tid = threadIdx.x;
    float m = -INFINITY;
    for (int i = tid; i < BV; i += 256) m = fmaxf(m, p[i]);
    red[tid] = m; __syncthreads();
    for (int st = 128; st > 0; st >>= 1) {
        if (tid < st) red[tid] = fmaxf(red[tid], red[tid + st]);
        __syncthreads();
    }
    float mx = red[0]; __syncthreads();
    float sum = 0.0f;
    for (int i = tid; i < BV; i += 256) sum += expf(p[i] - mx);
    red[tid] = sum; __syncthreads();
    for (int st = 128; st > 0; st >>= 1) {
        if (tid < st) red[tid] += red[tid + st];
        __syncthreads();
    }
    float lse = mx + logf(red[0]);
    for (int i = tid; i < BV; i += 256) p[i] -= lse;
}

// ---------------- launch ----------------
extern "C" void kernel_launch(void* const* d_in, const int* in_sizes, int n_in,
                              void* d_out, int out_size) {
    const float* att  = (const float*)d_in[0];
    const int*   seq  = (const int*)d_in[1];
    const float* E    = (const float*)d_in[2];
    const float* w_ih = (const float*)d_in[3];
    const float* w_hh = (const float*)d_in[4];
    const float* aeW  = (const float*)d_in[5];
    const float* aeb  = (const float*)d_in[6];
    const float* c2aW = (const float*)d_in[7];
    const float* c2ab = (const float*)d_in[8];
    const float* seW  = (const float*)d_in[9];
    const float* seb  = (const float*)d_in[10];
    const float* hoW  = (const float*)d_in[11];
    const float* hob  = (const float*)d_in[12];
    const float* alW  = (const float*)d_in[13];
    const float* alb  = (const float*)d_in[14];
    const float* a2hW = (const float*)d_in[15];
    const float* a2hb = (const float*)d_in[16];
    const float* lgW  = (const float*)d_in[17];
    const float* lgb  = (const float*)d_in[18];
    float* out = (float*)d_out;

    __nv_bfloat16 *att_bf, *aeW_bf, *c2aW_bf, *whh_bf, *seW_bf, *hoW_bf, *a2hW_bf;
    __nv_bfloat16 *v_bf, *vemb_bf, *xall_bf, *wih_bf, *lgW_bf, *hout_all, *h_bf, *sent_bf, *x2_bf;
    float *gx, *gates, *h, *c, *sentemb, *hemb;
    cudaGetSymbolAddress((void**)&att_bf, g_att_bf);
    cudaGetSymbolAddress((void**)&aeW_bf, g_aeW_bf);
    cudaGetSymbolAddress((void**)&c2aW_bf, g_c2aW_bf);
    cudaGetSymbolAddress((void**)&whh_bf, g_whh_bf);
    cudaGetSymbolAddress((void**)&seW_bf, g_seW_bf);
    cudaGetSymbolAddress((void**)&hoW_bf, g_hoW_bf);
    cudaGetSymbolAddress((void**)&a2hW_bf, g_a2hW_bf);
    cudaGetSymbolAddress((void**)&v_bf, g_v_bf);
    cudaGetSymbolAddress((void**)&vemb_bf, g_vemb_bf);
    cudaGetSymbolAddress((void**)&xall_bf, g_xall_bf);
    cudaGetSymbolAddress((void**)&wih_bf, g_wih_bf);
    cudaGetSymbolAddress((void**)&lgW_bf, g_lgW_bf);
    cudaGetSymbolAddress((void**)&hout_all, g_hout_all);
    cudaGetSymbolAddress((void**)&h_bf, g_h_bf);
    cudaGetSymbolAddress((void**)&sent_bf, g_sent_bf);
    cudaGetSymbolAddress((void**)&x2_bf, g_x2_bf);
    cudaGetSymbolAddress((void**)&gx, g_gx);
    cudaGetSymbolAddress((void**)&gates, g_gates);
    cudaGetSymbolAddress((void**)&h, g_h);
    cudaGetSymbolAddress((void**)&c, g_c);
    cudaGetSymbolAddress((void**)&sentemb, g_sentemb);
    cudaGetSymbolAddress((void**)&hemb, g_hemb);

    cudaFuncSetAttribute(step_loop_kernel,
                         cudaFuncAttributeMaxDynamicSharedMemorySize, SM_STEP);

    // fork stream B
    cudaEventRecord(s_evFork, 0);
    cudaStreamWaitEvent(s_b, s_evFork, 0);

    // Stream B: token path + loop/logits weight prep + gx GEMM
    pad_wih_bf<<<(G5 * DPK + 255) / 256, 256, 0, s_b>>>(w_ih, wih_bf);
    embed_all_bf<<<(TT * BB * DPK + 255) / 256, 256, 0, s_b>>>(seq, E, xall_bf);
    pad_lgw_bf<<<(BVP * RR + 255) / 256, 256, 0, s_b>>>(lgW, lgW_bf);
    cvt_f2b4<<<(G5 * RR / 4 + 255) / 256, 256, 0, s_b>>>(w_hh, whh_bf, G5 * RR / 4);
    cvt_f2b4<<<(HH * RR / 4 + 255) / 256, 256, 0, s_b>>>(seW, seW_bf, HH * RR / 4);
    cvt_f2b4<<<(HH * RR / 4 + 255) / 256, 256, 0, s_b>>>(hoW, hoW_bf, HH * RR / 4);
    cvt_f2b4<<<(RR * RR / 4 + 255) / 256, 256, 0, s_b>>>(a2hW, a2hW_bf, RR * RR / 4);
    gemm_mma<0, false, true, false, false, false>
        <<<dim3(TT * BB / 128, G5 / 128), 256, 0, s_b>>>(
        xall_bf, wih_bf, nullptr, nullptr, gx, nullptr, G5, DPK, G5, 0, 0);
    cudaEventRecord(s_evGx, s_b);

    // Stream A: image path (proven cvt + cp.async GEMM1)
    init_state_kernel<<<(BB * RR + 255) / 256, 256>>>(h, c, h_bf);
    cvt_f2b4<<<(MROWS * FEAT / 4 + 255) / 256, 256>>>(att, att_bf, MROWS * FEAT / 4);
    cvt_f2b4<<<(RR * FEAT / 4 + 255) / 256, 256>>>(aeW, aeW_bf, RR * FEAT / 4);
    cvt_f2b4<<<(RR * RR / 4 + 255) / 256, 256>>>(c2aW, c2aW_bf, RR * RR / 4);
    gemm_mma<1, true, false, true, false, false><<<dim3(MROWS / 128, RR / 128), 256>>>(
        att_bf, aeW_bf, aeb, nullptr, nullptr, v_bf, RR, FEAT, 0, 0, RR);
    gemm_mma<0, true, false, true, false, false><<<dim3(MROWS / 128, RR / 128), 256>>>(
        v_bf, c2aW_bf, c2ab, nullptr, nullptr, vemb_bf, RR, RR, 0, 0, RR);

    cudaStreamWaitEvent(0, s_evGx, 0);

    // Persistent recurrent loop (logits t=0..18, logsm t=0..17 folded into P5)
    step_loop_kernel<<<GRIDP, 256, SM_STEP>>>(
        whh_bf, gx, gates, h, c, h_bf, sent_bf, seW_bf, hoW_bf, seb, hob,
        sentemb, hemb, vemb_bf, alW, alb, v_bf, x2_bf, a2hW_bf, a2hb, hout_all,
        lgW_bf, lgb, out);

    // Tails: logits(19), logsm(18), logsm(19)
    gemm_mma<0, true, true, false, false, false>
        <<<dim3(1, BVP / 128), 256>>>(
        hout_all + (size_t)(TT - 1) * BB * RR, lgW_bf, lgb, nullptr,
        out + (size_t)(TT - 1) * BV, nullptr, BV, RR, OUT_ROW, 0, 0);
    logsm_all<<<dim3(BB, 2), 256>>>(out + (size_t)(TT - 2) * BV);
}

// round 17
// speedup vs baseline: 1.1070x; 1.1070x over previous
#include <cuda_runtime.h>
#include <cuda_bf16.h>
#include <math.h>
#include <stddef.h>
#include <stdint.h>

// Problem dims
#define BV 7800
#define BVP 7808
#define DD 300
#define DPK 320
#define RR 512
#define HH 512
#define FEAT 2048
#define BB 128
#define AA 196
#define TT 20
#define A1 197
#define G5 2560
#define MROWS 25088
#define OUT_ROW 156000
#define GRIDP 128

// ---------------- device scratch ----------------
__device__ __nv_bfloat16 g_att_bf[MROWS * FEAT];
__device__ __nv_bfloat16 g_aeW_bf[RR * FEAT];
__device__ __nv_bfloat16 g_c2aW_bf[RR * RR];
__device__ __nv_bfloat16 g_whh_bf[G5 * RR];
__device__ __nv_bfloat16 g_seW_bf[HH * RR];
__device__ __nv_bfloat16 g_hoW_bf[HH * RR];
__device__ __nv_bfloat16 g_a2hW_bf[RR * RR];
__device__ __nv_bfloat16 g_v_bf[MROWS * RR];
__device__ __nv_bfloat16 g_vemb_bf[MROWS * RR];
__device__ __nv_bfloat16 g_xall_bf[TT * BB * DPK];
__device__ __nv_bfloat16 g_wih_bf[G5 * DPK];
__device__ __nv_bfloat16 g_lgW_bf[BVP * RR];
__device__ __nv_bfloat16 g_hout_all[TT * BB * RR];
__device__ __nv_bfloat16 g_h_bf[BB * RR];
__device__ __nv_bfloat16 g_sent_bf[BB * RR];
__device__ __nv_bfloat16 g_x2_bf[BB * RR];
__device__ float g_gx[TT * BB * G5];
__device__ float g_gates[BB * G5];
__device__ float g_h[BB * RR];
__device__ float g_c[BB * RR];
__device__ float g_sentemb[BB * HH];
__device__ float g_hemb[BB * HH];
__device__ unsigned g_bar_count = 0;
__device__ volatile unsigned g_bar_sense = 0;

// ---------------- static stream/event resources ----------------
static cudaStream_t s_b = nullptr;
static cudaEvent_t s_evFork = nullptr, s_evGx = nullptr, s_evLoop = nullptr, s_evB2 = nullptr;
static struct StreamInit {
    StreamInit() {
        cudaStreamCreateWithFlags(&s_b, cudaStreamNonBlocking);
        cudaEventCreateWithFlags(&s_evFork, cudaEventDisableTiming);
        cudaEventCreateWithFlags(&s_evGx, cudaEventDisableTiming);
        cudaEventCreateWithFlags(&s_evLoop, cudaEventDisableTiming);
        cudaEventCreateWithFlags(&s_evB2, cudaEventDisableTiming);
    }
} s_streamInit;

// ---------------- helpers ----------------
__device__ __forceinline__ float sigmoidf_(float x) { return 1.0f / (1.0f + expf(-x)); }
__device__ __forceinline__ float tanh_fast(float x) {
    float y;
    asm("tanh.approx.f32 %0, %1;" : "=f"(y) : "f"(x));
    return y;
}
__device__ __forceinline__ void mma16816(float* c, const uint32_t* a, uint32_t b0, uint32_t b1) {
    asm volatile(
        "mma.sync.aligned.m16n8k16.row.col.f32.bf16.bf16.f32 "
        "{%0,%1,%2,%3}, {%4,%5,%6,%7}, {%8,%9}, {%0,%1,%2,%3};"
        : "+f"(c[0]), "+f"(c[1]), "+f"(c[2]), "+f"(c[3])
        : "r"(a[0]), "r"(a[1]), "r"(a[2]), "r"(a[3]), "r"(b0), "r"(b1));
}
__device__ __forceinline__ void ldsm4(uint32_t* r, uint32_t addr) {
    asm volatile("ldmatrix.sync.aligned.m8n8.x4.shared.b16 {%0,%1,%2,%3}, [%4];"
                 : "=r"(r[0]), "=r"(r[1]), "=r"(r[2]), "=r"(r[3]) : "r"(addr));
}
__device__ __forceinline__ void cpa16(uint32_t dst, const void* src) {
    asm volatile("cp.async.cg.shared.global [%0], [%1], 16;" :: "r"(dst), "l"(src));
}
#define CP_COMMIT() asm volatile("cp.async.commit_group;" ::: "memory")
#define CP_WAIT3()  asm volatile("cp.async.wait_group 3;" ::: "memory")
#define CP_WAIT1()  asm volatile("cp.async.wait_group 1;" ::: "memory")
#define CP_WAIT0()  asm volatile("cp.async.wait_group 0;" ::: "memory")

__device__ __forceinline__ void gbar(unsigned sense) {
    __syncthreads();
    if (threadIdx.x == 0) {
        __threadfence();
        unsigned arrived = atomicAdd(&g_bar_count, 1u);
        if (arrived == GRIDP - 1) {
            g_bar_count = 0;
            __threadfence();
            g_bar_sense = sense;
        } else {
            while (g_bar_sense != sense) __nanosleep(32);
        }
        __threadfence();
    }
    __syncthreads();
}

// ---------------- bf16 mma.sync GEMM: 128x128 tile, LDSM, 2-stage (proven) ----
#define PADR 40
#define BUFW (128 * PADR)
struct MmaSmem { __nv_bfloat16 sA[2][BUFW]; __nv_bfloat16 sB[2][BUFW]; };

template <int ACT, bool HAS_BIAS, bool WF32, bool WBF, bool HAS_CIN, bool OUTMAP>
__device__ __forceinline__ void mma_body(
    MmaSmem& sm,
    const __nv_bfloat16* __restrict__ A, const __nv_bfloat16* __restrict__ W,
    const float* __restrict__ bias, const float* __restrict__ Cin,
    float* __restrict__ C, __nv_bfloat16* __restrict__ Cbf,
    int Nlog, int K, size_t ldc, int ldcin, int ldbf, int bm, int bn) {

    int tid = threadIdx.x;
    int wid = tid >> 5, lane = tid & 31;
    int wm = wid >> 1, wn = wid & 1;
    int g = lane >> 2, tg = lane & 3;
    int lr8 = lane & 7;

    int r0g = tid >> 2, s0g = tid & 3;
    int r1g = (tid + 256) >> 2;
    const char* Ag0 = (const char*)(A + (size_t)(bm + r0g) * K + s0g * 8);
    const char* Ag1 = (const char*)(A + (size_t)(bm + r1g) * K + s0g * 8);
    const char* Wg0 = (const char*)(W + (size_t)(bn + r0g) * K + s0g * 8);
    const char* Wg1 = (const char*)(W + (size_t)(bn + r1g) * K + s0g * 8);
    uint32_t aBase = (uint32_t)__cvta_generic_to_shared(&sm.sA[0][0]);
    uint32_t bBase = (uint32_t)__cvta_generic_to_shared(&sm.sB[0][0]);
    uint32_t dA0 = aBase + r0g * (PADR * 2) + s0g * 16;
    uint32_t dA1 = aBase + r1g * (PADR * 2) + s0g * 16;
    uint32_t dB0 = bBase + r0g * (PADR * 2) + s0g * 16;
    uint32_t dB1 = bBase + r1g * (PADR * 2) + s0g * 16;

    uint32_t aAddr = aBase + (uint32_t)(wm * 32 + lr8 + ((lane >> 3) & 1) * 8) * 80
                     + (uint32_t)(lane >> 4) * 16;
    uint32_t bAddr = bBase + (uint32_t)(wn * 64 + lr8 + (lane >> 4) * 8) * 80
                     + (uint32_t)((lane >> 3) & 1) * 16;

    float acc[2][8][4];
#pragma unroll
    for (int m = 0; m < 2; m++)
#pragma unroll
        for (int n = 0; n < 8; n++)
#pragma unroll
            for (int q = 0; q < 4; q++) acc[m][n][q] = 0.0f;

    cpa16(dA0, Ag0); cpa16(dA1, Ag1);
    cpa16(dB0, Wg0); cpa16(dB1, Wg1);
    CP_COMMIT();

    for (int k0 = 0; k0 < K; k0 += 32) {
        int cur = (k0 >> 5) & 1;
        if (k0 + 32 < K) {
            uint32_t off = (cur ^ 1) * (BUFW * 2);
            size_t kb = (size_t)(k0 + 32) * 2;
            cpa16(dA0 + off, Ag0 + kb); cpa16(dA1 + off, Ag1 + kb);
            cpa16(dB0 + off, Wg0 + kb); cpa16(dB1 + off, Wg1 + kb);
            CP_COMMIT();
            CP_WAIT1();
        } else {
            CP_WAIT0();
        }
        __syncthreads();
        uint32_t so = cur * (BUFW * 2);
#pragma unroll
        for (int ks = 0; ks < 2; ks++) {
            uint32_t aF[2][4];
            ldsm4(aF[0], aAddr + so + ks * 32);
            ldsm4(aF[1], aAddr + so + 16 * 80 + ks * 32);
            uint32_t bF[4][4];
#pragma unroll
            for (int np = 0; np < 4; np++)
                ldsm4(bF[np], bAddr + so + np * 16 * 80 + ks * 32);
#pragma unroll
            for (int n = 0; n < 8; n++) {
                uint32_t b0 = bF[n >> 1][(n & 1) * 2];
                uint32_t b1 = bF[n >> 1][(n & 1) * 2 + 1];
                mma16816(acc[0][n], aF[0], b0, b1);
                mma16816(acc[1][n], aF[1], b0, b1);
            }
        }
        __syncthreads();
    }

#pragma unroll
    for (int m = 0; m < 2; m++) {
        int row0 = bm + wm * 32 + m * 16 + g;
#pragma unroll
        for (int n = 0; n < 8; n++) {
            int col = bn + wn * 64 + n * 8 + tg * 2;
            float v0 = acc[m][n][0], v1 = acc[m][n][1];
            float v2 = acc[m][n][2], v3 = acc[m][n][3];
            if (HAS_BIAS) {
                if (col < Nlog) { float bb = bias[col]; v0 += bb; v2 += bb; }
                if (col + 1 < Nlog) { float bb = bias[col + 1]; v1 += bb; v3 += bb; }
            }
            if (HAS_CIN) {
                float2 c0 = *(const float2*)(Cin + (size_t)row0 * ldcin + col);
                float2 c1 = *(const float2*)(Cin + (size_t)(row0 + 8) * ldcin + col);
                v0 += c0.x; v1 += c0.y; v2 += c1.x; v3 += c1.y;
            }
            if (ACT == 1) {
                v0 = fmaxf(v0, 0.f); v1 = fmaxf(v1, 0.f);
                v2 = fmaxf(v2, 0.f); v3 = fmaxf(v3, 0.f);
            } else if (ACT == 2) {
                v0 = tanhf(v0); v1 = tanhf(v1); v2 = tanhf(v2); v3 = tanhf(v3);
            }
            if (WF32) {
                size_t ra, rb2;
                if (OUTMAP) {
                    ra = (size_t)(row0 & 127) * OUT_ROW + (size_t)(row0 >> 7) * BV;
                    rb2 = (size_t)((row0 + 8) & 127) * OUT_ROW + (size_t)((row0 + 8) >> 7) * BV;
                } else {
                    ra = (size_t)row0 * ldc;
                    rb2 = (size_t)(row0 + 8) * ldc;
                }
                if (col + 1 < Nlog) {
                    *(float2*)(C + ra + col) = make_float2(v0, v1);
                    *(float2*)(C + rb2 + col) = make_float2(v2, v3);
                } else if (col < Nlog) {
                    C[ra + col] = v0;
                    C[rb2 + col] = v2;
                }
            }
            if (WBF) {
                *(__nv_bfloat162*)(Cbf + (size_t)row0 * ldbf + col) =
                    __floats2bfloat162_rn(v0, v1);
                *(__nv_bfloat162*)(Cbf + (size_t)(row0 + 8) * ldbf + col) =
                    __floats2bfloat162_rn(v2, v3);
            }
        }
    }
}

template <int ACT, bool HAS_BIAS, bool WF32, bool WBF, bool HAS_CIN, bool OUTMAP>
__global__ void __launch_bounds__(256, 2) gemm_mma(
    const __nv_bfloat16* __restrict__ A, const __nv_bfloat16* __restrict__ W,
    const float* __restrict__ bias, const float* __restrict__ Cin,
    float* __restrict__ C, __nv_bfloat16* __restrict__ Cbf,
    int Nlog, int K, size_t ldc, int ldcin, int ldbf) {
    __shared__ MmaSmem sm;
    mma_body<ACT, HAS_BIAS, WF32, WBF, HAS_CIN, OUTMAP>(
        sm, A, W, bias, Cin, C, Cbf, Nlog, K, ldc, ldcin, ldbf,
        blockIdx.x * 128, blockIdx.y * 128);
}

// ---------------- resident-B GEMM: 4-stage A pipeline, LDSM (proven) ----------
#define BROW 520
#define ASTAGES 4
template <int ACT, bool HAS_BIAS, bool WF32, bool WBF, bool HAS_CIN>
__device__ __forceinline__ void mma_resB(
    const __nv_bfloat16* __restrict__ sB, __nv_bfloat16* __restrict__ sAb,
    const __nv_bfloat16* __restrict__ A,
    const float* __restrict__ bias, const float* __restrict__ Cin,
    float* __restrict__ C, __nv_bfloat16* __restrict__ Cbf,
    size_t ldc, int ldcin, int ldbf, int bn) {

    int tid = threadIdx.x;
    int wid = tid >> 5, lane = tid & 31;
    int wm = wid >> 1, wn = wid & 1;
    int g = lane >> 2, tg = lane & 3;
    int lr8 = lane & 7;

    int r0g = tid >> 2, s0g = tid & 3;
    const char* Ag0 = (const char*)(A + (size_t)r0g * RR + s0g * 8);
    const char* Ag1 = (const char*)(A + (size_t)(r0g + 64) * RR + s0g * 8);
    uint32_t ab = (uint32_t)__cvta_generic_to_shared(sAb);
    uint32_t bb = (uint32_t)__cvta_generic_to_shared(sB);
    uint32_t dA0 = ab + r0g * (PADR * 2) + s0g * 16;
    uint32_t dA1 = ab + (r0g + 64) * (PADR * 2) + s0g * 16;

    uint32_t aAddr = ab + (uint32_t)(wm * 32 + lr8 + ((lane >> 3) & 1) * 8) * 80
                     + (uint32_t)(lane >> 4) * 16;
    uint32_t bAddr = bb + (uint32_t)(wn * 64 + lr8 + (lane >> 4) * 8) * 1040
                     + (uint32_t)((lane >> 3) & 1) * 16;

    float acc[2][8][4];
#pragma unroll
    for (int m = 0; m < 2; m++)
#pragma unroll
        for (int n = 0; n < 8; n++)
#pragma unroll
            for (int q = 0; q < 4; q++) acc[m][n][q] = 0.0f;

#pragma unroll
    for (int s = 0; s < 3; s++) {
        uint32_t off = s * (BUFW * 2);
        size_t kb = (size_t)(s << 5) * 2;
        cpa16(dA0 + off, Ag0 + kb); cpa16(dA1 + off, Ag1 + kb);
        CP_COMMIT();
    }

    for (int i = 0; i < 16; i++) {
        if (i + 3 < 16) {
            uint32_t off = ((i + 3) & 3) * (BUFW * 2);
            size_t kb = (size_t)((i + 3) << 5) * 2;
            cpa16(dA0 + off, Ag0 + kb); cpa16(dA1 + off, Ag1 + kb);
        }
        CP_COMMIT();
        CP_WAIT3();
        __syncthreads();
        uint32_t so = (i & 3) * (BUFW * 2);
        uint32_t kb64 = (uint32_t)i * 64;
#pragma unroll
        for (int ks = 0; ks < 2; ks++) {
            uint32_t aF[2][4];
            ldsm4(aF[0], aAddr + so + ks * 32);
            ldsm4(aF[1], aAddr + so + 16 * 80 + ks * 32);
            uint32_t bF[4][4];
#pragma unroll
            for (int np = 0; np < 4; np++)
                ldsm4(bF[np], bAddr + np * 16 * 1040 + kb64 + ks * 32);
#pragma unroll
            for (int n = 0; n < 8; n++) {
                uint32_t b0 = bF[n >> 1][(n & 1) * 2];
                uint32_t b1 = bF[n >> 1][(n & 1) * 2 + 1];
                mma16816(acc[0][n], aF[0], b0, b1);
                mma16816(acc[1][n], aF[1], b0, b1);
            }
        }
        __syncthreads();
    }

#pragma unroll
    for (int m = 0; m < 2; m++) {
        int row0 = wm * 32 + m * 16 + g;
#pragma unroll
        for (int n = 0; n < 8; n++) {
            int col = bn + wn * 64 + n * 8 + tg * 2;
            float v0 = acc[m][n][0], v1 = acc[m][n][1];
            float v2 = acc[m][n][2], v3 = acc[m][n][3];
            if (HAS_BIAS) {
                float b0 = bias[col], b1 = bias[col + 1];
                v0 += b0; v1 += b1; v2 += b0; v3 += b1;
            }
            if (HAS_CIN) {
                float2 c0 = *(const float2*)(Cin + (size_t)row0 * ldcin + col);
                float2 c1 = *(const float2*)(Cin + (size_t)(row0 + 8) * ldcin + col);
                v0 += c0.x; v1 += c0.y; v2 += c1.x; v3 += c1.y;
            }
            if (ACT == 2) { v0 = tanhf(v0); v1 = tanhf(v1); v2 = tanhf(v2); v3 = tanhf(v3); }
            if (WF32) {
                *(float2*)(C + (size_t)row0 * ldc + col) = make_float2(v0, v1);
                *(float2*)(C + (size_t)(row0 + 8) * ldc + col) = make_float2(v2, v3);
            }
            if (WBF) {
                *(__nv_bfloat162*)(Cbf + (size_t)row0 * ldbf + col) =
                    __floats2bfloat162_rn(v0, v1);
                *(__nv_bfloat162*)(Cbf + (size_t)(row0 + 8) * ldbf + col) =
                    __floats2bfloat162_rn(v2, v3);
            }
        }
    }
}

// ---------------- persistent step-loop (weights resident; in-loop logits) ----------------
#define SM_BRES 133120
#define SM_STEP (SM_BRES + ASTAGES * BUFW * 2)
struct AttnSmem { float sAl[HH]; float sH[HH]; float sSc[224]; float red[256]; };

__global__ void __launch_bounds__(256) step_loop_kernel(
    const __nv_bfloat16* __restrict__ whh_bf, const float* __restrict__ gx,
    float* __restrict__ gates, float* __restrict__ h, float* __restrict__ c,
    __nv_bfloat16* __restrict__ h_bf, __nv_bfloat16* __restrict__ sent_bf,
    const __nv_bfloat16* __restrict__ seW_bf, const __nv_bfloat16* __restrict__ hoW_bf,
    const float* __restrict__ seb, const float* __restrict__ hob,
    float* __restrict__ sentemb, float* __restrict__ hemb,
    const __nv_bfloat16* __restrict__ vemb_bf, const float* __restrict__ alW,
    const float* __restrict__ alb, const __nv_bfloat16* __restrict__ v_bf,
    __nv_bfloat16* __restrict__ x2_bf,
    const __nv_bfloat16* __restrict__ a2hW_bf, const float* __restrict__ a2hb,
    __nv_bfloat16* __restrict__ hout_all,
    const __nv_bfloat16* __restrict__ lgW_bf, const float* __restrict__ lgb,
    float* __restrict__ out) {
    extern __shared__ char dsm[];
    __nv_bfloat16* sB = (__nv_bfloat16*)dsm;
    __nv_bfloat16* sAb = (__nv_bfloat16*)(dsm + SM_BRES);
    AttnSmem* at = (AttnSmem*)(dsm + SM_BRES);
    MmaSmem* lsm = (MmaSmem*)dsm;   // logits CTAs (>=32): sB region is scratch

    int blk = blockIdx.x;
    int tid = threadIdx.x;
    unsigned sense = g_bar_sense;

    const __nv_bfloat16* myW = nullptr;
    if (blk < 20) myW = whh_bf + (size_t)blk * 128 * RR;
    else if (blk < 24) myW = seW_bf + (size_t)(blk - 20) * 128 * RR;
    else if (blk < 28) myW = hoW_bf + (size_t)(blk - 24) * 128 * RR;
    else if (blk < 32) myW = a2hW_bf + (size_t)(blk - 28) * 128 * RR;
    if (myW) {
        const uint4* src = (const uint4*)myW;
        for (int i = tid; i < 128 * 64; i += 256) {
            int r = i >> 6, cq = i & 63;
            ((uint4*)(sB + (size_t)r * BROW))[cq] = src[r * 64 + cq];
        }
    }
    __syncthreads();

    if (blk < 20)
        mma_resB<0, false, true, false, true>(sB, sAb, h_bf, nullptr, gx, gates,
                                              nullptr, G5, G5, 0, blk * 128);
    sense ^= 1; gbar(sense);

    for (int t = 0; t < TT; t++) {
        {
            int base = blk * 512 + tid;
#pragma unroll
            for (int u = 0; u < 2; u++) {
                int idx = base + u * 256;
                int b = idx >> 9, r = idx & 511;
                const float* gg = gates + (size_t)b * G5;
                float ig = sigmoidf_(gg[r]);
                float fg = sigmoidf_(gg[RR + r]);
                float g2 = tanhf(gg[2 * RR + r]);
                float og = sigmoidf_(gg[3 * RR + r]);
                float sg = sigmoidf_(gg[4 * RR + r]);
                float cy = tanhf(fg * c[idx] + ig * g2);
                c[idx] = cy;
                float hy = og * cy;
                h[idx] = hy;
                h_bf[idx] = __float2bfloat16(hy);
                sent_bf[idx] = __float2bfloat16(sg * cy);
            }
        }
        sense ^= 1; gbar(sense);

        if (blk >= 20 && blk < 24)
            mma_resB<0, true, true, false, false>(sB, sAb, sent_bf, seb, nullptr,
                                                  sentemb, nullptr, HH, 0, 0,
                                                  (blk - 20) * 128);
        else if (blk >= 24 && blk < 28)
            mma_resB<0, true, true, false, false>(sB, sAb, h_bf, hob, nullptr,
                                                  hemb, nullptr, HH, 0, 0,
                                                  (blk - 24) * 128);
        sense ^= 1; gbar(sense);

        {
            int b = blk;
            float* sAl = at->sAl;
            float* sH = at->sH;
            float* sSc = at->sSc;
            float* red = at->red;
            for (int j = tid; j < HH; j += 256) {
                sAl[j] = alW[j];
                sH[j] = hemb[(size_t)b * HH + j];
            }
            __syncthreads();
            int warp = tid >> 5, lane = tid & 31;
            float ab = alb[0];
            for (int a = warp; a < A1; a += 8) {
                float s = 0.0f;
                if (a == 0) {
                    const float2* e2 = (const float2*)(sentemb + (size_t)b * HH);
                    for (int j2 = lane; j2 < 256; j2 += 32) {
                        float2 ev = e2[j2];
                        int j = j2 * 2;
                        s += sAl[j] * tanh_fast(ev.x + sH[j]);
                        s += sAl[j + 1] * tanh_fast(ev.y + sH[j + 1]);
                    }
                } else {
                    const __nv_bfloat162* e2 =
                        (const __nv_bfloat162*)(vemb_bf + ((size_t)b * AA + (a - 1)) * HH);
                    for (int j2 = lane; j2 < 256; j2 += 32) {
                        __nv_bfloat162 ev = e2[j2];
                        int j = j2 * 2;
                        s += sAl[j] * tanh_fast(__low2float(ev) + sH[j]);
                        s += sAl[j + 1] * tanh_fast(__high2float(ev) + sH[j + 1]);
                    }
                }
#pragma unroll
                for (int o = 16; o > 0; o >>= 1) s += __shfl_down_sync(0xffffffffu, s, o);
                if (lane == 0) sSc[a] = s + ab;
            }
            __syncthreads();
            float m = -INFINITY;
            for (int a = tid; a < A1; a += 256) m = fmaxf(m, sSc[a]);
            red[tid] = m; __syncthreads();
            for (int st = 128; st > 0; st >>= 1) {
                if (tid < st) red[tid] = fmaxf(red[tid], red[tid + st]);
                __syncthreads();
            }
            float mx = red[0]; __syncthreads();
            float sum = 0.0f;
            for (int a = tid; a < A1; a += 256) sum += expf(sSc[a] - mx);
            red[tid] = sum; __syncthreads();
            for (int st = 128; st > 0; st >>= 1) {
                if (tid < st) red[tid] += red[tid + st];
                __syncthreads();
            }
            float inv = 1.0f / red[0];
            __syncthreads();
            for (int a = tid; a < A1; a += 256) sSc[a] = expf(sSc[a] - mx) * inv;
            __syncthreads();
            const __nv_bfloat162* vp2 = (const __nv_bfloat162*)(v_bf + (size_t)b * AA * RR);
            __nv_bfloat162 sv = ((const __nv_bfloat162*)(sent_bf + (size_t)b * RR))[tid];
            float a0 = sSc[0];
            float acc0 = a0 * __low2float(sv);
            float acc1 = a0 * __high2float(sv);
            for (int a = 0; a < AA; a++) {
                __nv_bfloat162 vv = vp2[(size_t)a * (RR / 2) + tid];
                float s = sSc[a + 1];
                acc0 += s * __low2float(vv);
                acc1 += s * __high2float(vv);
            }
            float2 hv = *(const float2*)(h + (size_t)b * RR + 2 * tid);
            ((__nv_bfloat162*)(x2_bf + (size_t)b * RR))[tid] =
                __floats2bfloat162_rn(acc0 + hv.x, acc1 + hv.y);
            __syncthreads();
        }
        sense ^= 1; gbar(sense);

        // Phase P5: a2h (CTAs 28-31) || P1(t+1) (CTAs 0-19) || logits(t-1) (CTAs 32-92)
        if (blk >= 28 && blk < 32)
            mma_resB<2, true, false, true, false>(sB, sAb, x2_bf, a2hb, nullptr,
                                                  nullptr, hout_all + (size_t)t * BB * RR,
                                                  0, 0, RR, (blk - 28) * 128);
        else if (blk < 20 && t + 1 < TT)
            mma_resB<0, false, true, false, true>(sB, sAb, h_bf, nullptr,
                                                  gx + (size_t)(t + 1) * BB * G5, gates,
                                                  nullptr, G5, G5, 0, blk * 128);
        else if (blk >= 32 && blk < 32 + BVP / 128 && t >= 1)
            mma_body<0, true, true, false, false, false>(
                *lsm, hout_all + (size_t)(t - 1) * BB * RR, lgW_bf, lgb, nullptr,
                out + (size_t)(t - 1) * BV, nullptr, BV, RR, OUT_ROW, 0, 0,
                0, (blk - 32) * 128);
        sense ^= 1; gbar(sense);
    }
}

// ---------------- conversions ----------------
__global__ void cvt_f2b4(const float* __restrict__ in, __nv_bfloat16* __restrict__ out, int n4) {
    int i = blockIdx.x * blockDim.x + threadIdx.x;
    if (i >= n4) return;
    float4 v = ((const float4*)in)[i];
    __nv_bfloat162* p = (__nv_bfloat162*)out + i * 2;
    p[0] = __floats2bfloat162_rn(v.x, v.y);
    p[1] = __floats2bfloat162_rn(v.z, v.w);
}
__global__ void pad_wih_bf(const float* __restrict__ w, __nv_bfloat16* __restrict__ wp) {
    int idx = blockIdx.x * blockDim.x + threadIdx.x;
    if (idx >= G5 * DPK) return;
    int r = idx / DPK, c = idx % DPK;
    wp[idx] = (c < DD) ? __float2bfloat16(w[r * DD + c]) : __float2bfloat16(0.0f);
}
__global__ void pad_lgw_bf(const float* __restrict__ w, __nv_bfloat16* __restrict__ wp) {
    int idx = blockIdx.x * blockDim.x + threadIdx.x;
    if (idx >= BVP * RR) return;
    int r = idx / RR, c = idx % RR;
    wp[idx] = (r < BV) ? __float2bfloat16(w[(size_t)r * RR + c]) : __float2bfloat16(0.0f);
}
__global__ void embed_all_bf(const int* __restrict__ seq, const float* __restrict__ E,
                             __nv_bfloat16* __restrict__ xall) {
    int idx = blockIdx.x * blockDim.x + threadIdx.x;
    if (idx >= TT * BB * DPK) return;
    int d = idx % DPK;
    int row = idx / DPK;
    int t = row / BB, b = row % BB;
    float v = 0.0f;
    if (d < DD) {
        int tok = seq[b * 21 + t];
        v = fmaxf(E[(size_t)tok * DD + d], 0.0f);
    }
    xall[idx] = __float2bfloat16(v);
}
__global__ void init_state_kernel(float* h, float* c, __nv_bfloat16* h_bf) {
    int i = blockIdx.x * blockDim.x + threadIdx.x;
    if (i < BB * RR) { h[i] = 0.0f; c[i] = 0.0f; h_bf[i] = __float2bfloat16(0.0f); }
}

// ---------------- batched log-softmax ----------------
__global__ void __launch_bounds__(256) logsm_all(float* __restrict__ out) {
    float* p = out + (size_t)blockIdx.x * OUT_ROW + (size_t)blockIdx.y * BV;
    __shared__ float red[256];
    int tid = threadIdx.x;
    float m = -INFINITY;
    for (int i = tid; i < BV; i += 256) m = fmaxf(m, p[i]);
    red[tid] = m; __syncthreads();
    for (int st = 128; st > 0; st >>= 1) {
        if (tid < st) red[tid] = fmaxf(red[tid], red[tid + st]);
        __syncthreads();
    }
    float mx = red[0]; __syncthreads();
    float sum = 0.0f;
    for (int i = tid; i < BV; i += 256) sum += expf(p[i] - mx);
    red[tid] = sum; __syncthreads();
    for (int st = 128; st > 0; st >>= 1) {
        if (tid < st) red[tid] += red[tid + st];
        __syncthreads();
    }
    float lse = mx + logf(red[0]);
    for (int i = tid; i < BV; i += 256) p[i] -= lse;
}

// ---------------- launch ----------------
extern "C" void kernel_launch(void* const* d_in, const int* in_sizes, int n_in,
                              void* d_out, int out_size) {
    const float* att  = (const float*)d_in[0];
    const int*   seq  = (const int*)d_in[1];
    const float* E    = (const float*)d_in[2];
    const float* w_ih = (const float*)d_in[3];
    const float* w_hh = (const float*)d_in[4];
    const float* aeW  = (const float*)d_in[5];
    const float* aeb  = (const float*)d_in[6];
    const float* c2aW = (const float*)d_in[7];
    const float* c2ab = (const float*)d_in[8];
    const float* seW  = (const float*)d_in[9];
    const float* seb  = (const float*)d_in[10];
    const float* hoW  = (const float*)d_in[11];
    const float* hob  = (const float*)d_in[12];
    const float* alW  = (const float*)d_in[13];
    const float* alb  = (const float*)d_in[14];
    const float* a2hW = (const float*)d_in[15];
    const float* a2hb = (const float*)d_in[16];
    const float* lgW  = (const float*)d_in[17];
    const float* lgb  = (const float*)d_in[18];
    float* out = (float*)d_out;

    __nv_bfloat16 *att_bf, *aeW_bf, *c2aW_bf, *whh_bf, *seW_bf, *hoW_bf, *a2hW_bf;
    __nv_bfloat16 *v_bf, *vemb_bf, *xall_bf, *wih_bf, *lgW_bf, *hout_all, *h_bf, *sent_bf, *x2_bf;
    float *gx, *gates, *h, *c, *sentemb, *hemb;
    cudaGetSymbolAddress((void**)&att_bf, g_att_bf);
    cudaGetSymbolAddress((void**)&aeW_bf, g_aeW_bf);
    cudaGetSymbolAddress((void**)&c2aW_bf, g_c2aW_bf);
    cudaGetSymbolAddress((void**)&whh_bf, g_whh_bf);
    cudaGetSymbolAddress((void**)&seW_bf, g_seW_bf);
    cudaGetSymbolAddress((void**)&hoW_bf, g_hoW_bf);
    cudaGetSymbolAddress((void**)&a2hW_bf, g_a2hW_bf);
    cudaGetSymbolAddress((void**)&v_bf, g_v_bf);
    cudaGetSymbolAddress((void**)&vemb_bf, g_vemb_bf);
    cudaGetSymbolAddress((void**)&xall_bf, g_xall_bf);
    cudaGetSymbolAddress((void**)&wih_bf, g_wih_bf);
    cudaGetSymbolAddress((void**)&lgW_bf, g_lgW_bf);
    cudaGetSymbolAddress((void**)&hout_all, g_hout_all);
    cudaGetSymbolAddress((void**)&h_bf, g_h_bf);
    cudaGetSymbolAddress((void**)&sent_bf, g_sent_bf);
    cudaGetSymbolAddress((void**)&x2_bf, g_x2_bf);
    cudaGetSymbolAddress((void**)&gx, g_gx);
    cudaGetSymbolAddress((void**)&gates, g_gates);
    cudaGetSymbolAddress((void**)&h, g_h);
    cudaGetSymbolAddress((void**)&c, g_c);
    cudaGetSymbolAddress((void**)&sentemb, g_sentemb);
    cudaGetSymbolAddress((void**)&hemb, g_hemb);

    cudaFuncSetAttribute(step_loop_kernel,
                         cudaFuncAttributeMaxDynamicSharedMemorySize, SM_STEP);

    // fork stream B
    cudaEventRecord(s_evFork, 0);
    cudaStreamWaitEvent(s_b, s_evFork, 0);

    // Stream B: token path + loop/logits weight prep + gx GEMM
    pad_wih_bf<<<(G5 * DPK + 255) / 256, 256, 0, s_b>>>(w_ih, wih_bf);
    embed_all_bf<<<(TT * BB * DPK + 255) / 256, 256, 0, s_b>>>(seq, E, xall_bf);
    pad_lgw_bf<<<(BVP * RR + 255) / 256, 256, 0, s_b>>>(lgW, lgW_bf);
    cvt_f2b4<<<(G5 * RR / 4 + 255) / 256, 256, 0, s_b>>>(w_hh, whh_bf, G5 * RR / 4);
    cvt_f2b4<<<(HH * RR / 4 + 255) / 256, 256, 0, s_b>>>(seW, seW_bf, HH * RR / 4);
    cvt_f2b4<<<(HH * RR / 4 + 255) / 256, 256, 0, s_b>>>(hoW, hoW_bf, HH * RR / 4);
    cvt_f2b4<<<(RR * RR / 4 + 255) / 256, 256, 0, s_b>>>(a2hW, a2hW_bf, RR * RR / 4);
    gemm_mma<0, false, true, false, false, false>
        <<<dim3(TT * BB / 128, G5 / 128), 256, 0, s_b>>>(
        xall_bf, wih_bf, nullptr, nullptr, gx, nullptr, G5, DPK, G5, 0, 0);
    cudaEventRecord(s_evGx, s_b);

    // Stream A: image path
    init_state_kernel<<<(BB * RR + 255) / 256, 256>>>(h, c, h_bf);
    cvt_f2b4<<<(MROWS * FEAT / 4 + 255) / 256, 256>>>(att, att_bf, MROWS * FEAT / 4);
    cvt_f2b4<<<(RR * FEAT / 4 + 255) / 256, 256>>>(aeW, aeW_bf, RR * FEAT / 4);
    cvt_f2b4<<<(RR * RR / 4 + 255) / 256, 256>>>(c2aW, c2aW_bf, RR * RR / 4);
    gemm_mma<1, true, false, true, false, false><<<dim3(MROWS / 128, RR / 128), 256>>>(
        att_bf, aeW_bf, aeb, nullptr, nullptr, v_bf, RR, FEAT, 0, 0, RR);
    gemm_mma<0, true, false, true, false, false><<<dim3(MROWS / 128, RR / 128), 256>>>(
        v_bf, c2aW_bf, c2ab, nullptr, nullptr, vemb_bf, RR, RR, 0, 0, RR);

    cudaStreamWaitEvent(0, s_evGx, 0);

    // Persistent recurrent loop (logits for t=0..18 folded into P5 phases)
    step_loop_kernel<<<GRIDP, 256, SM_STEP>>>(
        whh_bf, gx, gates, h, c, h_bf, sent_bf, seW_bf, hoW_bf, seb, hob,
        sentemb, hemb, vemb_bf, alW, alb, v_bf, x2_bf, a2hW_bf, a2hb, hout_all,
        lgW_bf, lgb, out);
    cudaEventRecord(s_evLoop, 0);

    // Stream B: log-softmax for t=0..18 (independent of logits(19) on A)
    cudaStreamWaitEvent(s_b, s_evLoop, 0);
    logsm_all<<<dim3(BB, TT - 1), 256, 0, s_b>>>(out);
    cudaEventRecord(s_evB2, s_b);

    // Stream A: logits(19), then logsm(19)
    gemm_mma<0, true, true, false, false, false>
        <<<dim3(1, BVP / 128), 256>>>(
        hout_all + (size_t)(TT - 1) * BB * RR, lgW_bf, lgb, nullptr,
        out + (size_t)(TT - 1) * BV, nullptr, BV, RR, OUT_ROW, 0, 0);
    logsm_all<<<dim3(BB, 1), 256>>>(out + (size_t)(TT - 1) * BV);

    cudaStreamWaitEvent(0, s_evB2, 0);
}